// round 15
// baseline (speedup 1.0000x reference)
#include <cuda_runtime.h>
#include <cuda_bf16.h>
#include <cuda_fp16.h>

#define R_ROWS 4
#define NROWS  (R_ROWS + 2)
#define NCELL  42            // cells of width 0.4 covering v in [-8.2, 8.2)

template<int N> struct IC { static constexpr int value = N; };

// KAN 3x3 conv, shared KANLinear(9->1), cubic B-spline on uniform grid.
// FULLY FUSED per-cell cubic: value_f(v) = silu(v)*bw[f] + spline_f(v), one
// cubic per (cell, feature). silu part: interpolating cubic (err ~2e-5);
// spline part: exact on in-grid cells (J in [15,25], j=J-15). All tables fp16
// (16 B per pair gather, same LDS budget as R14); Horner in half2 for pairs,
// fp32 combine. Sends pair-packed on full-kh rows.
__global__ __launch_bounds__(128, 7)
void kan_conv_kernel(const float* __restrict__ x,
                     const float* __restrict__ bw,
                     const float* __restrict__ sw,
                     const float* __restrict__ ss,
                     float* __restrict__ out)
{
    __shared__ float4 stg[NCELL * 9];    // fp32 staging of fused coeffs
    __shared__ uint2  polyF[NCELL * 9];  // scalar fused table: {h2(a0,a1), h2(a2,a3)}
    __shared__ uint4  pairE[NCELL * 3];  // even px acc pair (f=3kh lo, f=3kh+1 hi)
    __shared__ uint4  pairO[NCELL * 3];  // odd  px acc pair (f=3kh+1 lo, f=3kh+2 hi)
    __shared__ uint4  sLp[NCELL];        // send-left pair (f2 lo, f5 hi)
    __shared__ uint4  sRp[NCELL];        // send-right pair (f0 lo, f3 hi)
    __shared__ float  Zs[9];             // fused value at padding pixels (x=0)

    const int lane  = threadIdx.x & 31;
    const int warp  = threadIdx.x >> 5;
    const int img   = blockIdx.x >> 2;                  // 1024 blocks = 256 images x 4
    const int strip = ((blockIdx.x & 3) << 2) | warp;   // 0..15
    const int y0    = strip * R_ROWS;

    // ---- stage fused fp32 cubics ----
    for (int t = threadIdx.x; t < NCELL * 9; t += 128) {
        const int J = t / 9, f = t - J * 9;
        const float bwf = __ldg(&bw[f]);
        const float v0  = 0.4f * J - 8.2f;         // v = v0 + 0.4*u

        // silu*bw interpolating cubic through u = 0, 1/3, 2/3, 1
        float s[4];
        #pragma unroll
        for (int k = 0; k < 4; k++) {
            float v = v0 + 0.4f * (k * (1.f / 3.f));
            s[k] = (v / (1.f + __expf(-v))) * bwf;
        }
        const float d1 = s[1] - s[0], d2 = s[2] - s[0], d3 = s[3] - s[0];
        float a0 = s[0];
        float a1 = 9.f * d1 - 4.5f * d2 + d3;
        float a2 = 13.5f * d1 - 0.5f * d3 - 4.f * a1;
        float a3 = d3 - a1 - a2;

        // exact spline part on in-grid cells (original cell j = J-15)
        if (J >= 15 && J <= 25) {
            const int j = J - 15;
            float scale = __ldg(&ss[f]);
            float W[4];
            #pragma unroll
            for (int c = 0; c < 4; c++) {
                int bi = j + c - 3;
                W[c] = (bi >= 0 && bi < 8) ? __ldg(&sw[f * 8 + bi]) * scale : 0.f;
            }
            const float S = 1.f / 6.f;
            a0 += (W[0] + 4.f * W[1] + W[2]) * S;
            a1 += (W[2] - W[0]) * 0.5f;
            a2 += (W[0] - 2.f * W[1] + W[2]) * 0.5f;
            a3 += (W[3] - W[0] + 3.f * (W[1] - W[2])) * S;
        }
        stg[t] = make_float4(a0, a1, a2, a3);
    }
    __syncthreads();

    // ---- pack fp16 tables ----
    auto h2u = [](float a, float b) {
        __half2 h = __floats2half2_rn(a, b);
        return *reinterpret_cast<unsigned*>(&h);
    };
    auto pack4 = [&h2u](const float4& lo, const float4& hi) {
        uint4 q;
        q.x = h2u(lo.x, hi.x);
        q.y = h2u(lo.y, hi.y);
        q.z = h2u(lo.z, hi.z);
        q.w = h2u(lo.w, hi.w);
        return q;
    };
    for (int t = threadIdx.x; t < NCELL * 9; t += 128) {
        float4 c = stg[t];
        polyF[t] = make_uint2(h2u(c.x, c.y), h2u(c.z, c.w));
    }
    for (int t = threadIdx.x; t < NCELL * 3; t += 128) {
        const int J = t / 3, kh = t - J * 3;
        pairE[t] = pack4(stg[J * 9 + kh * 3 + 0], stg[J * 9 + kh * 3 + 1]);
        pairO[t] = pack4(stg[J * 9 + kh * 3 + 1], stg[J * 9 + kh * 3 + 2]);
    }
    for (int t = threadIdx.x; t < NCELL; t += 128) {
        sLp[t] = pack4(stg[t * 9 + 2], stg[t * 9 + 5]);
        sRp[t] = pack4(stg[t * 9 + 0], stg[t * 9 + 3]);
    }
    if (threadIdx.x < 9) {
        // x=0 -> cell J=20, u=0.5 (fp32 exact from staging)
        float4 c = stg[20 * 9 + threadIdx.x];
        Zs[threadIdx.x] = fmaf(fmaf(fmaf(c.w, 0.5f, c.z), 0.5f, c.y), 0.5f, c.x);
    }
    __syncthreads();

    float Z[9];
    #pragma unroll
    for (int f = 0; f < 9; f++) Z[f] = Zs[f];

    const float* xcol = x   + img * 4096 + lane * 2;
    float*       ocol = out + img * 4096 + lane * 2;

    float accE[3] = {0.f, 0.f, 0.f};
    float accO[3] = {0.f, 0.f, 0.f};

    // half2 pair Horner (2 features at once)
    auto evalP = [](const uint4& q, __half2 u2) -> __half2 {
        __half2 t = __hfma2(*reinterpret_cast<const __half2*>(&q.w), u2,
                            *reinterpret_cast<const __half2*>(&q.z));
        t = __hfma2(t, u2, *reinterpret_cast<const __half2*>(&q.y));
        t = __hfma2(t, u2, *reinterpret_cast<const __half2*>(&q.x));
        return t;
    };
    // scalar fused eval (fp16 coeffs, fp32 Horner)
    auto evalSc = [&](int idx, float u) {
        uint2 pk = polyF[idx];
        float2 c01 = __half22float2(*reinterpret_cast<__half2*>(&pk.x));
        float2 c23 = __half22float2(*reinterpret_cast<__half2*>(&pk.y));
        float t = fmaf(c23.y, u, c23.x);
        t = fmaf(t, u, c01.y);
        return fmaf(t, u, c01.x);
    };

    auto row = [&](auto rc) {
        constexpr int r = rc.value;
        const int py = y0 - 1 + r;
        float2 p;
        if constexpr (r == 0 || r == NROWS - 1) {
            p = make_float2(0.f, 0.f);
            if (py >= 0 && py < 64) p = *(const float2*)(xcol + py * 64);
        } else {
            p = *(const float2*)(xcol + py * 64);
        }

        // cell locate: xc = (v + 8.2)/0.4, clamped into [0, 42)
        float xce = fminf(fmaxf(fmaf(p.x, 2.5f, 20.5f), 0.f), 41.99f);
        float jfe = floorf(xce);
        const float ue = xce - jfe;
        const int  je  = (int)jfe;
        float xco = fminf(fmaxf(fmaf(p.y, 2.5f, 20.5f), 0.f), 41.99f);
        float jfo = floorf(xco);
        const float uo = xco - jfo;
        const int  jo  = (int)jfo;

        const __half2 u2e = __float2half2_rn(ue);
        const __half2 u2o = __float2half2_rn(uo);
        const int je3 = je * 3, jo3 = jo * 3;
        const int je9 = je * 9, jo9 = jo * 9;

        // out = py+1-kh in strip => kh in [r-3, r] ∩ [0,2]
        constexpr int kh_lo = (r > 3) ? (r - 3) : 0;
        constexpr int kh_hi = (r < 2) ? r : 2;

        // send evals: pair-packed on full-kh rows, scalar otherwise
        float sLv[3], sRv[3];
        if constexpr (kh_lo == 0 && kh_hi == 2) {
            float2 l01 = __half22float2(evalP(sLp[je], u2e));
            sLv[0] = l01.x; sLv[1] = l01.y;
            sLv[2] = evalSc(je9 + 8, ue);
            float2 r01 = __half22float2(evalP(sRp[jo], u2o));
            sRv[0] = r01.x; sRv[1] = r01.y;
            sRv[2] = evalSc(jo9 + 6, uo);
        } else {
            #pragma unroll
            for (int kh = kh_lo; kh <= kh_hi; kh++) {
                sLv[kh] = evalSc(je9 + kh * 3 + 2, ue);
                sRv[kh] = evalSc(jo9 + kh * 3 + 0, uo);
            }
        }

        #pragma unroll
        for (int kh = kh_lo; kh <= kh_hi; kh++) {
            float2 fe = __half22float2(evalP(pairE[je3 + kh], u2e));
            float2 fo = __half22float2(evalP(pairO[jo3 + kh], u2o));

            float rl = __shfl_down_sync(0xffffffffu, sLv[kh], 1);
            if (lane == 31) rl = Z[kh * 3 + 2];      // col 64 padding -> out col 63
            float rr = __shfl_up_sync(0xffffffffu, sRv[kh], 1);
            if (lane == 0)  rr = Z[kh * 3 + 0];      // col -1 padding -> out col 0

            accO[2 - kh] += (fe.x + fo.x) + rl;
            accE[2 - kh] += (fe.y + fo.y) + rr;
        }

        if constexpr (r >= 2) {
            *(float2*)(ocol + (y0 + r - 2) * 64) = make_float2(accE[0], accO[0]);
        }
        accE[0] = accE[1]; accE[1] = accE[2]; accE[2] = 0.f;
        accO[0] = accO[1]; accO[1] = accO[2]; accO[2] = 0.f;
    };

    row(IC<0>{}); row(IC<1>{}); row(IC<2>{});
    row(IC<3>{}); row(IC<4>{}); row(IC<5>{});
}

extern "C" void kernel_launch(void* const* d_in, const int* in_sizes, int n_in,
                              void* d_out, int out_size) {
    const float* x  = (const float*)d_in[0];  // (8,32,64,64)
    const float* bw = (const float*)d_in[1];  // (1,9)
    const float* sw = (const float*)d_in[2];  // (1,9,8)
    const float* ss = (const float*)d_in[3];  // (1,9)
    float* out = (float*)d_out;

    // 256 images x 16 strips, 4 warp-strips per block
    kan_conv_kernel<<<1024, 128>>>(x, bw, sw, ss, out);
}

// round 16
// speedup vs baseline: 1.4479x; 1.4479x over previous
#include <cuda_runtime.h>
#include <cuda_bf16.h>
#include <cuda_fp16.h>

#define R_ROWS 4
#define NROWS  (R_ROWS + 2)

template<int N> struct IC { static constexpr int value = N; };

// silu via fast approx: v * rcp(1 + 2^(-v*log2e))
__device__ __forceinline__ float fast_silu(float v) {
    float e, r;
    asm("ex2.approx.f32 %0, %1;" : "=f"(e) : "f"(v * -1.442695041f));
    asm("rcp.approx.f32 %0, %1;" : "=f"(r) : "f"(1.0f + e));
    return v * r;
}

// Cubic coeffs of spline_f on cell j (j=11 -> all zero row):
// a0=(W0+4W1+W2)/6, a1=(W2-W0)/2, a2=(W0-2W1+W2)/2, a3=(W3-W0+3(W1-W2))/6
__device__ __forceinline__ void spline_coeffs(int j, int f,
                                              const float* __restrict__ sw,
                                              const float* __restrict__ ss,
                                              float a[4]) {
    a[0] = a[1] = a[2] = a[3] = 0.f;
    if (j < 11) {
        float scale = __ldg(&ss[f]);
        float W[4];
        #pragma unroll
        for (int c = 0; c < 4; c++) {
            int bi = j + c - 3;
            W[c] = (bi >= 0 && bi < 8) ? __ldg(&sw[f * 8 + bi]) * scale : 0.f;
        }
        const float S = 1.f / 6.f;
        a[0] = (W[0] + 4.f * W[1] + W[2]) * S;
        a[1] = (W[2] - W[0]) * 0.5f;
        a[2] = (W[0] - 2.f * W[1] + W[2]) * 0.5f;
        a[3] = (W[3] - W[0] + 3.f * (W[1] - W[2])) * S;
    }
}

// KAN 3x3 conv, shared KANLinear(9->1), cubic B-spline on uniform grid.
// R14 skeleton (warp-per-strip rolling, R=4, kh-trim, fp16 tables, half2
// pair Horner) + send pair-packing on full-kh rows + reg diet (Z in smem,
// launch_bounds 8 blocks/SM).
__global__ __launch_bounds__(128, 8)
void kan_conv_kernel(const float* __restrict__ x,
                     const float* __restrict__ bw,
                     const float* __restrict__ sw,
                     const float* __restrict__ ss,
                     float* __restrict__ out)
{
    __shared__ uint2 polyH[12 * 9];   // scalar table: [j][f] = {h2(a0,a1), h2(a2,a3)}
    __shared__ uint4 pairE[12 * 3];   // even px acc pair (lo=f3kh ->accO, hi=f3kh+1 ->accE)
    __shared__ uint4 pairO[12 * 3];   // odd  px acc pair (lo=f3kh+1->accO, hi=f3kh+2 ->accE)
    __shared__ uint4 sLp[12];         // send-left pair (f2 lo, f5 hi), spline only
    __shared__ uint4 sRp[12];         // send-right pair (f0 lo, f3 hi), spline only
    __shared__ float Zs[9];           // spline value at padding pixels (x=0)

    const int lane  = threadIdx.x & 31;
    const int warp  = threadIdx.x >> 5;
    const int img   = blockIdx.x >> 2;                  // 1024 blocks = 256 images x 4
    const int strip = ((blockIdx.x & 3) << 2) | warp;   // 0..15
    const int y0    = strip * R_ROWS;

    auto h2u = [](float a, float b) {
        __half2 h = __floats2half2_rn(a, b);
        return *reinterpret_cast<unsigned*>(&h);
    };

    // ---- scalar table + padding constants ----
    if (threadIdx.x < 108) {
        const int t = threadIdx.x;
        const int j = t / 9, f = t - j * 9;
        float a[4];
        spline_coeffs(j, f, sw, ss, a);
        polyH[t] = make_uint2(h2u(a[0], a[1]), h2u(a[2], a[3]));
        if (j == 5)   // x=0 -> cell 5, u=0.5, silu=0 (fp32 exact)
            Zs[f] = fmaf(fmaf(fmaf(a[3], 0.5f, a[2]), 0.5f, a[1]), 0.5f, a[0]);
    }
    // ---- packed acc-pair tables ----
    if (threadIdx.x < 72) {
        const int which = threadIdx.x / 36;        // 0 = even pair, 1 = odd pair
        const int e = threadIdx.x % 36;
        const int j = e / 3, kh = e - j * 3;
        const int flo = kh * 3 + which;
        float clo[4], chi[4];
        spline_coeffs(j, flo,     sw, ss, clo);
        spline_coeffs(j, flo + 1, sw, ss, chi);
        uint4 q;
        q.x = h2u(clo[0], chi[0]);
        q.y = h2u(clo[1], chi[1]);
        q.z = h2u(clo[2], chi[2]);
        q.w = h2u(clo[3], chi[3]);
        (which ? pairO : pairE)[j * 3 + kh] = q;
    }
    // ---- packed send-pair tables ----
    if (threadIdx.x >= 72 && threadIdx.x < 96) {
        const int t = threadIdx.x - 72;
        const int which = t / 12;                  // 0 = sL (f2,f5), 1 = sR (f0,f3)
        const int j = t % 12;
        const int flo = which ? 0 : 2;
        float clo[4], chi[4];
        spline_coeffs(j, flo,     sw, ss, clo);
        spline_coeffs(j, flo + 3, sw, ss, chi);
        uint4 q;
        q.x = h2u(clo[0], chi[0]);
        q.y = h2u(clo[1], chi[1]);
        q.z = h2u(clo[2], chi[2]);
        q.w = h2u(clo[3], chi[3]);
        (which ? sRp : sLp)[j] = q;
    }
    float bwr[9];
    #pragma unroll
    for (int f = 0; f < 9; f++) bwr[f] = __ldg(&bw[f]);
    __syncthreads();

    const float* xcol = x   + img * 4096 + lane * 2;
    float*       ocol = out + img * 4096 + lane * 2;

    float accE[3] = {0.f, 0.f, 0.f};
    float accO[3] = {0.f, 0.f, 0.f};

    // scalar eval (fp16 coeffs, fp32 Horner, base folded)
    auto evalS = [&](int jbase, float u, float s, int f) {
        uint2 pk = polyH[jbase + f];
        float2 c01 = __half22float2(*reinterpret_cast<__half2*>(&pk.x));
        float2 c23 = __half22float2(*reinterpret_cast<__half2*>(&pk.y));
        float t = fmaf(c23.y, u, c23.x);
        t = fmaf(t, u, c01.y);
        t = fmaf(t, u, c01.x);
        return fmaf(s, bwr[f], t);
    };
    // half2 pair Horner (2 features at once)
    auto evalP = [](const uint4& q, __half2 u2) -> __half2 {
        __half2 t = __hfma2(*reinterpret_cast<const __half2*>(&q.w), u2,
                            *reinterpret_cast<const __half2*>(&q.z));
        t = __hfma2(t, u2, *reinterpret_cast<const __half2*>(&q.y));
        t = __hfma2(t, u2, *reinterpret_cast<const __half2*>(&q.x));
        return t;
    };

    auto row = [&](auto rc) {
        constexpr int r = rc.value;
        const int py = y0 - 1 + r;
        float2 p;
        if constexpr (r == 0 || r == NROWS - 1) {
            p = make_float2(0.f, 0.f);
            if (py >= 0 && py < 64) p = *(const float2*)(xcol + py * 64);
        } else {
            p = *(const float2*)(xcol + py * 64);
        }

        const float se = fast_silu(p.x);
        const float so = fast_silu(p.y);

        // cell locate; out-of-grid -> row 11 (all-zero coeffs)
        float xce = fmaf(p.x, 2.5f, 5.5f);          // (v+2.2)/0.4
        float jfe = floorf(xce);
        const float ue = xce - jfe;
        const int je = min((unsigned)(int)jfe, 11u);
        float xco = fmaf(p.y, 2.5f, 5.5f);
        float jfo = floorf(xco);
        const float uo = xco - jfo;
        const int jo = min((unsigned)(int)jfo, 11u);

        const __half2 u2e = __float2half2_rn(ue);
        const __half2 u2o = __float2half2_rn(uo);
        const int je3 = je * 3, jo3 = jo * 3;
        const int je9 = je * 9, jo9 = jo * 9;

        // out = py+1-kh in strip => kh in [r-3, r] ∩ [0,2]
        constexpr int kh_lo = (r > 3) ? (r - 3) : 0;
        constexpr int kh_hi = (r < 2) ? r : 2;

        // send evals
        float sLv[3], sRv[3];
        if constexpr (kh_lo == 0 && kh_hi == 2) {
            float2 l01 = __half22float2(evalP(sLp[je], u2e));   // spline f2, f5
            sLv[0] = fmaf(se, bwr[2], l01.x);
            sLv[1] = fmaf(se, bwr[5], l01.y);
            sLv[2] = evalS(je9, ue, se, 8);
            float2 r01 = __half22float2(evalP(sRp[jo], u2o));   // spline f0, f3
            sRv[0] = fmaf(so, bwr[0], r01.x);
            sRv[1] = fmaf(so, bwr[3], r01.y);
            sRv[2] = evalS(jo9, uo, so, 6);
        } else {
            #pragma unroll
            for (int kh = kh_lo; kh <= kh_hi; kh++) {
                sLv[kh] = evalS(je9, ue, se, kh * 3 + 2);
                sRv[kh] = evalS(jo9, uo, so, kh * 3 + 0);
            }
        }

        #pragma unroll
        for (int kh = kh_lo; kh <= kh_hi; kh++) {
            __half2 spe = evalP(pairE[je3 + kh], u2e);
            __half2 spo = evalP(pairO[jo3 + kh], u2o);
            float2 sp = __half22float2(__hadd2(spe, spo));

            float aO = accO[2 - kh] + sp.x;
            aO = fmaf(se, bwr[kh * 3 + 0], aO);
            aO = fmaf(so, bwr[kh * 3 + 1], aO);
            float aE = accE[2 - kh] + sp.y;
            aE = fmaf(se, bwr[kh * 3 + 1], aE);
            aE = fmaf(so, bwr[kh * 3 + 2], aE);

            float rl = __shfl_down_sync(0xffffffffu, sLv[kh], 1);
            if (lane == 31) rl = Zs[kh * 3 + 2];     // col 64 padding -> out col 63
            float rr = __shfl_up_sync(0xffffffffu, sRv[kh], 1);
            if (lane == 0)  rr = Zs[kh * 3 + 0];     // col -1 padding -> out col 0

            accO[2 - kh] = aO + rl;
            accE[2 - kh] = aE + rr;
        }

        if constexpr (r >= 2) {
            *(float2*)(ocol + (y0 + r - 2) * 64) = make_float2(accE[0], accO[0]);
        }
        accE[0] = accE[1]; accE[1] = accE[2]; accE[2] = 0.f;
        accO[0] = accO[1]; accO[1] = accO[2]; accO[2] = 0.f;
    };

    row(IC<0>{}); row(IC<1>{}); row(IC<2>{});
    row(IC<3>{}); row(IC<4>{}); row(IC<5>{});
}

extern "C" void kernel_launch(void* const* d_in, const int* in_sizes, int n_in,
                              void* d_out, int out_size) {
    const float* x  = (const float*)d_in[0];  // (8,32,64,64)
    const float* bw = (const float*)d_in[1];  // (1,9)
    const float* sw = (const float*)d_in[2];  // (1,9,8)
    const float* ss = (const float*)d_in[3];  // (1,9)
    float* out = (float*)d_out;

    // 256 images x 16 strips, 4 warp-strips per block
    kan_conv_kernel<<<1024, 128>>>(x, bw, sw, ss, out);
}